// round 14
// baseline (speedup 1.0000x reference)
#include <cuda_runtime.h>
#include <cuda_bf16.h>
#include <cstdint>
#include <cstddef>

#define NN 100000
#define EE 1600000
#define HH 128
#define GG 128
#define SCAN_BLK 1024
#define SCAN_NB ((NN + SCAN_BLK - 1) / SCAN_BLK)   // 98

// ---------------------------------------------------------------------------
// Scratch (__device__ globals; allocation-free rule)
// ---------------------------------------------------------------------------
__device__ float g_h[(size_t)NN * HH];              // layer output ping
__device__ float g_h2[(size_t)NN * HH];             // layer output pong
__device__ __nv_bfloat16 g_wH[6 * HH * HH];         // transposed weights hi ([n][k])
__device__ __nv_bfloat16 g_wL[6 * HH * HH];         // transposed weights lo
__device__ float g_rcp[GG];                         // 1/max(count,1) per graph
__device__ int g_deg[NN];
__device__ int g_rowptr[NN];
__device__ int g_head[NN];
__device__ int g_csrc[EE];
__device__ int g_bsum[SCAN_NB];

// ---------------------------------------------------------------------------
// helpers
// ---------------------------------------------------------------------------
__device__ __forceinline__ uint32_t smem_u32(const void* p) {
    uint32_t a;
    asm("{ .reg .u64 t; cvta.to.shared.u64 t, %1; cvt.u32.u64 %0, t; }" : "=r"(a) : "l"(p));
    return a;
}

__device__ __forceinline__ void ldsm4(uint32_t* r, uint32_t addr) {
    asm volatile("ldmatrix.sync.aligned.m8n8.x4.shared.b16 {%0,%1,%2,%3}, [%4];"
                 : "=r"(r[0]), "=r"(r[1]), "=r"(r[2]), "=r"(r[3]) : "r"(addr));
}

__device__ __forceinline__ void mma16816(float* c, const uint32_t* a, uint32_t b0, uint32_t b1) {
    asm volatile("mma.sync.aligned.m16n8k16.row.col.f32.bf16.bf16.f32 "
                 "{%0,%1,%2,%3}, {%4,%5,%6,%7}, {%8,%9}, {%0,%1,%2,%3};"
                 : "+f"(c[0]), "+f"(c[1]), "+f"(c[2]), "+f"(c[3])
                 : "r"(a[0]), "r"(a[1]), "r"(a[2]), "r"(a[3]), "r"(b0), "r"(b1));
}

__device__ __forceinline__ uint32_t pk(__nv_bfloat16 a, __nv_bfloat16 b) {
    __nv_bfloat162 t(a, b);
    return *reinterpret_cast<uint32_t*>(&t);
}

__device__ __forceinline__ uint32_t split_hi(float v0, float v1, uint32_t& lo) {
    __nv_bfloat16 h0 = __float2bfloat16(v0), h1 = __float2bfloat16(v1);
    lo = pk(__float2bfloat16(v0 - __bfloat162float(h0)),
            __float2bfloat16(v1 - __bfloat162float(h1)));
    return pk(h0, h1);
}

// ---------------------------------------------------------------------------
// CSR build (once per launch): edges grouped by destination
// ---------------------------------------------------------------------------
__global__ void zero_deg_kernel(int* __restrict__ deg) {
    int i = blockIdx.x * blockDim.x + threadIdx.x;
    if (i < NN) deg[i] = 0;
}

__global__ void hist_kernel(const int4* __restrict__ dst4, int* __restrict__ deg) {
    int i = blockIdx.x * blockDim.x + threadIdx.x;
    if (i < EE / 4) {
        int4 d = __ldg(dst4 + i);
        atomicAdd(&deg[d.x], 1);
        atomicAdd(&deg[d.y], 1);
        atomicAdd(&deg[d.z], 1);
        atomicAdd(&deg[d.w], 1);
    }
}

__global__ void scan1_kernel(const int* __restrict__ deg, int* __restrict__ rowptr,
                             int* __restrict__ bsum) {
    __shared__ int sh[SCAN_BLK];
    int i = blockIdx.x * SCAN_BLK + threadIdx.x;
    int v = (i < NN) ? deg[i] : 0;
    sh[threadIdx.x] = v;
    __syncthreads();
    #pragma unroll
    for (int off = 1; off < SCAN_BLK; off <<= 1) {
        int t = (threadIdx.x >= off) ? sh[threadIdx.x - off] : 0;
        __syncthreads();
        sh[threadIdx.x] += t;
        __syncthreads();
    }
    if (i < NN) rowptr[i] = sh[threadIdx.x] - v;       // exclusive
    if (threadIdx.x == SCAN_BLK - 1) bsum[blockIdx.x] = sh[SCAN_BLK - 1];
}

__global__ void scan3_kernel(int* __restrict__ rowptr, int* __restrict__ head,
                             const int* __restrict__ bsum) {
    __shared__ int sh[128], ex[128];
    int tid = threadIdx.x;
    if (tid < 128) {
        int vv = (tid < SCAN_NB) ? bsum[tid] : 0;
        sh[tid] = vv;
        ex[tid] = vv;
    }
    __syncthreads();
    #pragma unroll
    for (int off = 1; off < 128; off <<= 1) {
        int t = (tid >= off && tid < 128) ? sh[tid - off] : 0;
        __syncthreads();
        if (tid < 128) sh[tid] += t;
        __syncthreads();
    }
    if (tid < 128) ex[tid] = sh[tid] - ex[tid];        // exclusive
    __syncthreads();
    int i = blockIdx.x * blockDim.x + tid;
    if (i < NN) {
        int r = rowptr[i] + ex[i >> 10];
        rowptr[i] = r;
        head[i] = r;
    }
}

__global__ void fill_kernel(const int4* __restrict__ src4, const int4* __restrict__ dst4,
                            int* __restrict__ head, int* __restrict__ csrc) {
    int i = blockIdx.x * blockDim.x + threadIdx.x;
    if (i < EE / 4) {
        int4 s = __ldg(src4 + i);
        int4 d = __ldg(dst4 + i);
        csrc[atomicAdd(&head[d.x], 1)] = s.x;
        csrc[atomicAdd(&head[d.y], 1)] = s.y;
        csrc[atomicAdd(&head[d.z], 1)] = s.z;
        csrc[atomicAdd(&head[d.w], 1)] = s.w;
    }
}

__global__ void rcp_kernel(const int* __restrict__ batch, float* __restrict__ rcp) {
    int g = threadIdx.x;
    if (g >= GG) return;
    int lo = 0, hi = NN;
    while (lo < hi) { int m = (lo + hi) >> 1; if (batch[m] < g) lo = m + 1; else hi = m; }
    int start = lo;
    lo = start; hi = NN;
    while (lo < hi) { int m = (lo + hi) >> 1; if (batch[m] < g + 1) lo = m + 1; else hi = m; }
    int cnt = lo - start;
    rcp[g] = 1.f / (float)max(cnt, 1);
}

// ---------------------------------------------------------------------------
// Weights: transpose + split. out[m][n][k] = W_m[k][n]
// ---------------------------------------------------------------------------
__global__ void wconv_kernel(const float* __restrict__ W0, const float* __restrict__ W1,
                             const float* __restrict__ W2, const float* __restrict__ W3,
                             const float* __restrict__ W4, const float* __restrict__ W5,
                             __nv_bfloat16* __restrict__ wh, __nv_bfloat16* __restrict__ wl) {
    int i = blockIdx.x * blockDim.x + threadIdx.x;
    if (i >= 6 * HH * HH) return;
    int m = i / (HH * HH);
    int r = i % (HH * HH);
    int n = r / HH;
    int k = r % HH;
    const float* W = (m == 0) ? W0 : (m == 1) ? W1 : (m == 2) ? W2
                   : (m == 3) ? W3 : (m == 4) ? W4 : W5;
    float v = W[k * HH + n];
    __nv_bfloat16 h = __float2bfloat16(v);
    wh[i] = h;
    wl[i] = __float2bfloat16(v - __bfloat162float(h));
}

// ---------------------------------------------------------------------------
// Fully fused GIN layer (persistent): Out = relu((In+agg) @ W1 + b1) @ W2 + b2
// Gather is a per-tile prologue: 16 warps x 4 rows each read neighbor rows
// from In (fp32, L2-resident), accumulate, split hi/lo DIRECTLY into smem A.
// No global intermediate. 2 syncs/tile. MLP core identical to R8.
// Smem: A 34816 + MID 34816 + W1 69632 + W2 69632 = 208896 B. 512 threads.
// ---------------------------------------------------------------------------
#define PITCH 272
#define S_A   0
#define S_MID 34816
#define S_W1H 69632
#define S_W1L 104448
#define S_W2H 139264
#define S_W2L 174080
#define FUSED_SMEM 208896
#define MTILE 64
#define NTILES ((NN + MTILE - 1) / MTILE)   // 1563

__device__ __forceinline__ void run_gemm(uint32_t aHb, uint32_t aLb,
                                         uint32_t bHb, uint32_t bLb,
                                         float (&accH)[4][4], float (&accL)[4][4]) {
    #pragma unroll
    for (int i = 0; i < 4; i++)
        #pragma unroll
        for (int j = 0; j < 4; j++) { accH[i][j] = 0.f; accL[i][j] = 0.f; }
    #pragma unroll
    for (int ks = 0; ks < 8; ks++) {
        uint32_t aH[4], aL[4];
        ldsm4(aH, aHb + ks * 32);
        ldsm4(aL, aLb + ks * 32);
        #pragma unroll
        for (int np = 0; np < 2; np++) {
            uint32_t bh[4], bl[4];
            ldsm4(bh, bHb + np * (16 * PITCH) + ks * 32);
            ldsm4(bl, bLb + np * (16 * PITCH) + ks * 32);
            mma16816(accH[2 * np],     aH, bh[0], bh[2]);
            mma16816(accL[2 * np],     aL, bh[0], bh[2]);
            mma16816(accL[2 * np],     aH, bl[0], bl[2]);
            mma16816(accH[2 * np + 1], aH, bh[1], bh[3]);
            mma16816(accL[2 * np + 1], aL, bh[1], bh[3]);
            mma16816(accL[2 * np + 1], aH, bl[1], bl[3]);
        }
    }
}

__global__ __launch_bounds__(512, 1)
void fused_layer_persist(const float* __restrict__ In,
                         const int* __restrict__ csrc, const int* __restrict__ rowptr,
                         const int* __restrict__ deg,
                         const __nv_bfloat16* __restrict__ W1h, const __nv_bfloat16* __restrict__ W1l,
                         const __nv_bfloat16* __restrict__ W2h, const __nv_bfloat16* __restrict__ W2l,
                         const float* __restrict__ bias1, const float* __restrict__ bias2,
                         float* __restrict__ Out, int M) {
    extern __shared__ __align__(16) char smem[];
    const uint32_t sb = smem_u32(smem);
    const int tid = threadIdx.x;
    const int wid = tid >> 5, lane = tid & 31;

    // ---- stage all weights once ----
    #pragma unroll
    for (int it = 0; it < 4; it++) {
        int idx = it * 512 + tid;       // 0..2047
        int row = idx >> 4, c = idx & 15;
        size_t go = (size_t)row * HH + c * 8;
        *reinterpret_cast<uint4*>(smem + S_W1H + row * PITCH + c * 16) =
            *reinterpret_cast<const uint4*>(W1h + go);
        *reinterpret_cast<uint4*>(smem + S_W1L + row * PITCH + c * 16) =
            *reinterpret_cast<const uint4*>(W1l + go);
        *reinterpret_cast<uint4*>(smem + S_W2H + row * PITCH + c * 16) =
            *reinterpret_cast<const uint4*>(W2h + go);
        *reinterpret_cast<uint4*>(smem + S_W2L + row * PITCH + c * 16) =
            *reinterpret_cast<const uint4*>(W2l + go);
    }

    const int wr = wid >> 2;            // 0..3 (16 rows each)
    const int wc = wid & 3;             // 0..3 (32 cols each)
    const int arow = lane & 15;
    const int akc  = (lane & 16) >> 1;  // 0 or 8
    const int quad = lane >> 2;
    const int qc   = (lane & 3) * 2;

    const uint32_t aHb = sb + S_A   + (wr * 16 + arow) * PITCH + akc * 2;
    const uint32_t aLb = aHb + 17408;
    const uint32_t mHb = sb + S_MID + (wr * 16 + arow) * PITCH + akc * 2;
    const uint32_t mLb = mHb + 17408;
    const uint32_t w1Hb = sb + S_W1H + (wc * 32 + arow) * PITCH + akc * 2;
    const uint32_t w1Lb = sb + S_W1L + (wc * 32 + arow) * PITCH + akc * 2;
    const uint32_t w2Hb = sb + S_W2H + (wc * 32 + arow) * PITCH + akc * 2;
    const uint32_t w2Lb = sb + S_W2L + (wc * 32 + arow) * PITCH + akc * 2;

    const float4* base = reinterpret_cast<const float4*>(In);

    int t = blockIdx.x;
    while (t < NTILES) {
        // ---- gather phase: warp handles 4 rows; lane = float4 chunk ----
        #pragma unroll
        for (int k = 0; k < 4; k++) {
            int row = wid * 4 + k;
            int node = t * MTILE + row;
            float4 a0 = make_float4(0.f, 0.f, 0.f, 0.f);
            float4 a1 = a0, a2 = a0, a3 = a0;
            if (node < M) {
                a0 = base[(size_t)node * 32 + lane];        // self term
                int st = rowptr[node];
                int dg = deg[node];
                int j = 0;
                for (; j + 4 <= dg; j += 4) {
                    int s0 = __ldg(csrc + st + j);
                    int s1 = __ldg(csrc + st + j + 1);
                    int s2 = __ldg(csrc + st + j + 2);
                    int s3 = __ldg(csrc + st + j + 3);
                    float4 v0 = base[(size_t)s0 * 32 + lane];
                    float4 v1 = base[(size_t)s1 * 32 + lane];
                    float4 v2 = base[(size_t)s2 * 32 + lane];
                    float4 v3 = base[(size_t)s3 * 32 + lane];
                    a0.x += v0.x; a0.y += v0.y; a0.z += v0.z; a0.w += v0.w;
                    a1.x += v1.x; a1.y += v1.y; a1.z += v1.z; a1.w += v1.w;
                    a2.x += v2.x; a2.y += v2.y; a2.z += v2.z; a2.w += v2.w;
                    a3.x += v3.x; a3.y += v3.y; a3.z += v3.z; a3.w += v3.w;
                }
                for (; j < dg; j++) {
                    int s = __ldg(csrc + st + j);
                    float4 v = base[(size_t)s * 32 + lane];
                    a0.x += v.x; a0.y += v.y; a0.z += v.z; a0.w += v.w;
                }
                a0.x += a1.x + a2.x + a3.x;
                a0.y += a1.y + a2.y + a3.y;
                a0.z += a1.z + a2.z + a3.z;
                a0.w += a1.w + a2.w + a3.w;
            }
            uint32_t lo0, lo1;
            uint32_t hi0 = split_hi(a0.x, a0.y, lo0);
            uint32_t hi1 = split_hi(a0.z, a0.w, lo1);
            uint32_t off = row * PITCH + lane * 8;
            *reinterpret_cast<uint2*>(smem + S_A + off) = make_uint2(hi0, hi1);
            *reinterpret_cast<uint2*>(smem + S_A + 17408 + off) = make_uint2(lo0, lo1);
        }
        __syncthreads();                                  // B1: A(t) ready (+ weights on iter 0)

        float accH[4][4], accL[4][4];

        // ---- GEMM1: A x W1 ----
        run_gemm(aHb, aLb, w1Hb, w1Lb, accH, accL);

        // ---- epilogue 1: relu(acc+b1) -> hi/lo -> MID buffer ----
        {
            const int lr0 = wr * 16 + quad;
            #pragma unroll
            for (int np = 0; np < 2; np++) {
                #pragma unroll
                for (int s = 0; s < 2; s++) {
                    int nt = 2 * np + s;
                    int col = wc * 32 + np * 16 + s * 8 + qc;
                    float b0 = __ldg(bias1 + col), b1v = __ldg(bias1 + col + 1);
                    float v00 = fmaxf(accH[nt][0] + accL[nt][0] + b0, 0.f);
                    float v01 = fmaxf(accH[nt][1] + accL[nt][1] + b1v, 0.f);
                    float v10 = fmaxf(accH[nt][2] + accL[nt][2] + b0, 0.f);
                    float v11 = fmaxf(accH[nt][3] + accL[nt][3] + b1v, 0.f);
                    uint32_t lo0, lo1;
                    uint32_t hi0 = split_hi(v00, v01, lo0);
                    uint32_t hi1 = split_hi(v10, v11, lo1);
                    char* mb = smem + S_MID;
                    *reinterpret_cast<uint32_t*>(mb + lr0 * PITCH + col * 2) = hi0;
                    *reinterpret_cast<uint32_t*>(mb + 17408 + lr0 * PITCH + col * 2) = lo0;
                    *reinterpret_cast<uint32_t*>(mb + (lr0 + 8) * PITCH + col * 2) = hi1;
                    *reinterpret_cast<uint32_t*>(mb + 17408 + (lr0 + 8) * PITCH + col * 2) = lo1;
                }
            }
        }
        __syncthreads();                                  // B2: mid visible, A reads done

        // ---- GEMM2: mid x W2 ----
        run_gemm(mHb, mLb, w2Hb, w2Lb, accH, accL);

        // ---- epilogue 2: + b2 -> fp32 gmem ----
        {
            const int r0 = t * MTILE + wr * 16 + quad;
            const int r1 = r0 + 8;
            #pragma unroll
            for (int np = 0; np < 2; np++) {
                #pragma unroll
                for (int s = 0; s < 2; s++) {
                    int nt = 2 * np + s;
                    int col = wc * 32 + np * 16 + s * 8 + qc;
                    float b0 = __ldg(bias2 + col), b1v = __ldg(bias2 + col + 1);
                    if (r0 < M)
                        *reinterpret_cast<float2*>(Out + (size_t)r0 * HH + col) =
                            make_float2(accH[nt][0] + accL[nt][0] + b0,
                                        accH[nt][1] + accL[nt][1] + b1v);
                    if (r1 < M)
                        *reinterpret_cast<float2*>(Out + (size_t)r1 * HH + col) =
                            make_float2(accH[nt][2] + accL[nt][2] + b0,
                                        accH[nt][3] + accL[nt][3] + b1v);
                }
            }
        }
        t += gridDim.x;
    }
}

// ---------------------------------------------------------------------------
// Pooling (batch sorted): partials pre-scaled by 1/count -> mean via atomics.
// ---------------------------------------------------------------------------
__global__ void pool_kernel(const float* __restrict__ h, const int* __restrict__ batch,
                            const float* __restrict__ rcp, float* __restrict__ out) {
    __shared__ int sbv[128];
    const int b0 = blockIdx.x * 128;
    const int c = threadIdx.x;
    const int nrows = min(128, NN - b0);
    if (c < nrows) sbv[c] = batch[b0 + c];
    __syncthreads();

    int cur = sbv[0];
    float acc = 0.f;
    for (int i = 0; i < nrows; i++) {
        int g = sbv[i];
        if (g != cur) {
            atomicAdd(&out[cur * 128 + c], acc * rcp[cur]);
            acc = 0.f; cur = g;
        }
        acc += h[(size_t)(b0 + i) * 128 + c];
    }
    atomicAdd(&out[cur * 128 + c], acc * rcp[cur]);
}

__global__ void zero_out_kernel(float* __restrict__ out) {
    int i = blockIdx.x * blockDim.x + threadIdx.x;
    if (i < GG * HH) out[i] = 0.f;
}

// ---------------------------------------------------------------------------
// Launch
// ---------------------------------------------------------------------------
extern "C" void kernel_launch(void* const* d_in, const int* in_sizes, int n_in,
                              void* d_out, int out_size) {
    (void)in_sizes; (void)n_in; (void)out_size;

    const float* x          = (const float*)d_in[0];
    const int*   edge_index = (const int*)d_in[1];
    const int*   batch      = (const int*)d_in[2];
    const int*   e_src = edge_index;
    const int*   e_dst = edge_index + EE;
    float* out = (float*)d_out;

    void *ph, *ph2, *pwH, *pwL, *prcp, *pdeg, *prp, *phd, *pcs, *pbs;
    cudaGetSymbolAddress(&ph,  g_h);
    cudaGetSymbolAddress(&ph2, g_h2);
    cudaGetSymbolAddress(&pwH, g_wH);
    cudaGetSymbolAddress(&pwL, g_wL);
    cudaGetSymbolAddress(&prcp, g_rcp);
    cudaGetSymbolAddress(&pdeg, g_deg);
    cudaGetSymbolAddress(&prp,  g_rowptr);
    cudaGetSymbolAddress(&phd,  g_head);
    cudaGetSymbolAddress(&pcs,  g_csrc);
    cudaGetSymbolAddress(&pbs,  g_bsum);
    float* h  = (float*)ph;
    float* h2 = (float*)ph2;
    __nv_bfloat16* wH = (__nv_bfloat16*)pwH;
    __nv_bfloat16* wL = (__nv_bfloat16*)pwL;
    float* rcp = (float*)prcp;
    int* deg    = (int*)pdeg;
    int* rowptr = (int*)prp;
    int* head   = (int*)phd;
    int* csrc   = (int*)pcs;
    int* bsum   = (int*)pbs;

    cudaFuncSetAttribute(fused_layer_persist,
                         cudaFuncAttributeMaxDynamicSharedMemorySize, FUSED_SMEM);

    const int nn_blocks    = (NN + 255) / 256;
    const int e4_blocks    = (EE / 4 + 255) / 256;
    const int wconv_blocks = (6 * HH * HH + 255) / 256;

    // ---- CSR build + per-graph reciprocal counts (once) ----
    zero_deg_kernel<<<nn_blocks, 256>>>(deg);
    hist_kernel<<<e4_blocks, 256>>>((const int4*)e_dst, deg);
    scan1_kernel<<<SCAN_NB, SCAN_BLK>>>(deg, rowptr, bsum);
    scan3_kernel<<<nn_blocks, 256>>>(rowptr, head, bsum);
    fill_kernel<<<e4_blocks, 256>>>((const int4*)e_src, (const int4*)e_dst, head, csrc);
    rcp_kernel<<<1, 128>>>(batch, rcp);

    wconv_kernel<<<wconv_blocks, 256>>>((const float*)d_in[3], (const float*)d_in[5],
                                        (const float*)d_in[7], (const float*)d_in[9],
                                        (const float*)d_in[11], (const float*)d_in[13],
                                        wH, wL);

    // Layer ping-pong: x -> h -> h2 -> h
    const float* ins[3]  = { x, h, h2 };
    float*       outs[3] = { h, h2, h };
    for (int l = 0; l < 3; l++) {
        const float* b1 = (const float*)d_in[3 + 4 * l + 1];
        const float* b2 = (const float*)d_in[3 + 4 * l + 3];
        __nv_bfloat16* w1H = wH + (size_t)(2 * l) * HH * HH;
        __nv_bfloat16* w1L = wL + (size_t)(2 * l) * HH * HH;
        __nv_bfloat16* w2H = wH + (size_t)(2 * l + 1) * HH * HH;
        __nv_bfloat16* w2L = wL + (size_t)(2 * l + 1) * HH * HH;

        fused_layer_persist<<<148, 512, FUSED_SMEM>>>(
            ins[l], csrc, rowptr, deg,
            w1H, w1L, w2H, w2L, b1, b2, outs[l], NN);
    }

    zero_out_kernel<<<(GG * HH + 255) / 256, 256>>>(out);
    pool_kernel<<<(NN + 127) / 128, 128>>>(h, batch, rcp, out);
}

// round 15
// speedup vs baseline: 1.3477x; 1.3477x over previous
#include <cuda_runtime.h>
#include <cuda_bf16.h>
#include <cstdint>
#include <cstddef>

#define NN 100000
#define EE 1600000
#define HH 128
#define GG 128
#define SCAN_BLK 1024
#define SCAN_NB ((NN + SCAN_BLK - 1) / SCAN_BLK)   // 98

// ---------------------------------------------------------------------------
// Scratch (__device__ globals; allocation-free rule)
// ---------------------------------------------------------------------------
__device__ float g_h[(size_t)NN * HH];              // layer output (fp32)
__device__ __nv_bfloat16 g_aH[(size_t)NN * HH];     // xagg hi split
__device__ __nv_bfloat16 g_aL[(size_t)NN * HH];     // xagg lo split
__device__ __nv_bfloat16 g_wH[6 * HH * HH];         // transposed weights hi ([n][k])
__device__ __nv_bfloat16 g_wL[6 * HH * HH];         // transposed weights lo
__device__ float g_cnt[GG];
__device__ int g_deg[NN];
__device__ int g_rowptr[NN];
__device__ int g_head[NN];
__device__ int g_csrc[EE];
__device__ int g_bsum[SCAN_NB];

// ---------------------------------------------------------------------------
// helpers
// ---------------------------------------------------------------------------
__device__ __forceinline__ uint32_t smem_u32(const void* p) {
    uint32_t a;
    asm("{ .reg .u64 t; cvta.to.shared.u64 t, %1; cvt.u32.u64 %0, t; }" : "=r"(a) : "l"(p));
    return a;
}

__device__ __forceinline__ void ldsm4(uint32_t* r, uint32_t addr) {
    asm volatile("ldmatrix.sync.aligned.m8n8.x4.shared.b16 {%0,%1,%2,%3}, [%4];"
                 : "=r"(r[0]), "=r"(r[1]), "=r"(r[2]), "=r"(r[3]) : "r"(addr));
}

__device__ __forceinline__ void mma16816(float* c, const uint32_t* a, uint32_t b0, uint32_t b1) {
    asm volatile("mma.sync.aligned.m16n8k16.row.col.f32.bf16.bf16.f32 "
                 "{%0,%1,%2,%3}, {%4,%5,%6,%7}, {%8,%9}, {%0,%1,%2,%3};"
                 : "+f"(c[0]), "+f"(c[1]), "+f"(c[2]), "+f"(c[3])
                 : "r"(a[0]), "r"(a[1]), "r"(a[2]), "r"(a[3]), "r"(b0), "r"(b1));
}

__device__ __forceinline__ uint32_t pk(__nv_bfloat16 a, __nv_bfloat16 b) {
    __nv_bfloat162 t(a, b);
    return *reinterpret_cast<uint32_t*>(&t);
}

__device__ __forceinline__ uint32_t split_hi(float v0, float v1, uint32_t& lo) {
    __nv_bfloat16 h0 = __float2bfloat16(v0), h1 = __float2bfloat16(v1);
    lo = pk(__float2bfloat16(v0 - __bfloat162float(h0)),
            __float2bfloat16(v1 - __bfloat162float(h1)));
    return pk(h0, h1);
}

__device__ __forceinline__ void cp16(uint32_t dst, const void* src, int sz) {
    asm volatile("cp.async.cg.shared.global [%0], [%1], 16, %2;"
                 :: "r"(dst), "l"(src), "r"(sz) : "memory");
}
#define CP_COMMIT() asm volatile("cp.async.commit_group;" ::: "memory")
#define CP_WAIT0()  asm volatile("cp.async.wait_group 0;" ::: "memory")

// ---------------------------------------------------------------------------
// CSR build (once per launch): edges grouped by destination
// ---------------------------------------------------------------------------
__global__ void zero_deg_kernel(int* __restrict__ deg) {
    int i = blockIdx.x * blockDim.x + threadIdx.x;
    if (i < NN) deg[i] = 0;
}

__global__ void hist_kernel(const int* __restrict__ dst, int* __restrict__ deg) {
    int i = blockIdx.x * blockDim.x + threadIdx.x;
    if (i < EE) atomicAdd(&deg[dst[i]], 1);
}

__global__ void scan1_kernel(const int* __restrict__ deg, int* __restrict__ rowptr,
                             int* __restrict__ bsum) {
    __shared__ int sh[SCAN_BLK];
    int i = blockIdx.x * SCAN_BLK + threadIdx.x;
    int v = (i < NN) ? deg[i] : 0;
    sh[threadIdx.x] = v;
    __syncthreads();
    #pragma unroll
    for (int off = 1; off < SCAN_BLK; off <<= 1) {
        int t = (threadIdx.x >= off) ? sh[threadIdx.x - off] : 0;
        __syncthreads();
        sh[threadIdx.x] += t;
        __syncthreads();
    }
    if (i < NN) rowptr[i] = sh[threadIdx.x] - v;       // exclusive
    if (threadIdx.x == SCAN_BLK - 1) bsum[blockIdx.x] = sh[SCAN_BLK - 1];
}

// scan3 with the 98-element block-sum prefix computed redundantly per block
// (no separate scan2 launch).
__global__ void scan3_kernel(int* __restrict__ rowptr, int* __restrict__ head,
                             const int* __restrict__ bsum) {
    __shared__ int sh[128], ex[128];
    int tid = threadIdx.x;
    if (tid < 128) {
        int vv = (tid < SCAN_NB) ? bsum[tid] : 0;
        sh[tid] = vv;
        ex[tid] = vv;
    }
    __syncthreads();
    #pragma unroll
    for (int off = 1; off < 128; off <<= 1) {
        int t = (tid >= off && tid < 128) ? sh[tid - off] : 0;
        __syncthreads();
        if (tid < 128) sh[tid] += t;
        __syncthreads();
    }
    if (tid < 128) ex[tid] = sh[tid] - ex[tid];        // exclusive
    __syncthreads();
    int i = blockIdx.x * blockDim.x + tid;
    if (i < NN) {
        int r = rowptr[i] + ex[i >> 10];
        rowptr[i] = r;
        head[i] = r;
    }
}

__global__ void fill_kernel(const int* __restrict__ src, const int* __restrict__ dst,
                            int* __restrict__ head, int* __restrict__ csrc) {
    int i = blockIdx.x * blockDim.x + threadIdx.x;
    if (i < EE) {
        int pos = atomicAdd(&head[dst[i]], 1);
        csrc[pos] = src[i];
    }
}

// ---------------------------------------------------------------------------
// gather: warp per node. xagg[i] = in[i] + sum_{j in csr(i)} in[j]
// Output written as bf16 hi/lo split (MLP A-operand ready).
// ---------------------------------------------------------------------------
__global__ __launch_bounds__(256)
void gather_kernel(const float* __restrict__ In, const int* __restrict__ csrc,
                   const int* __restrict__ rowptr, const int* __restrict__ deg,
                   __nv_bfloat16* __restrict__ outH, __nv_bfloat16* __restrict__ outL) {
    int node = (blockIdx.x * blockDim.x + threadIdx.x) >> 5;
    int lane = threadIdx.x & 31;
    if (node >= NN) return;
    const float4* base = reinterpret_cast<const float4*>(In);

    float4 a0 = base[(size_t)node * 32 + lane];    // self term
    float4 a1 = make_float4(0.f, 0.f, 0.f, 0.f);
    float4 a2 = a1, a3 = a1;

    int st = rowptr[node];
    int dg = deg[node];
    int j = 0;
    for (; j + 4 <= dg; j += 4) {
        int s0 = __ldg(csrc + st + j);
        int s1 = __ldg(csrc + st + j + 1);
        int s2 = __ldg(csrc + st + j + 2);
        int s3 = __ldg(csrc + st + j + 3);
        float4 v0 = base[(size_t)s0 * 32 + lane];
        float4 v1 = base[(size_t)s1 * 32 + lane];
        float4 v2 = base[(size_t)s2 * 32 + lane];
        float4 v3 = base[(size_t)s3 * 32 + lane];
        a0.x += v0.x; a0.y += v0.y; a0.z += v0.z; a0.w += v0.w;
        a1.x += v1.x; a1.y += v1.y; a1.z += v1.z; a1.w += v1.w;
        a2.x += v2.x; a2.y += v2.y; a2.z += v2.z; a2.w += v2.w;
        a3.x += v3.x; a3.y += v3.y; a3.z += v3.z; a3.w += v3.w;
    }
    for (; j < dg; j++) {
        int s = __ldg(csrc + st + j);
        float4 v = base[(size_t)s * 32 + lane];
        a0.x += v.x; a0.y += v.y; a0.z += v.z; a0.w += v.w;
    }
    a0.x += a1.x + a2.x + a3.x;
    a0.y += a1.y + a2.y + a3.y;
    a0.z += a1.z + a2.z + a3.z;
    a0.w += a1.w + a2.w + a3.w;

    uint32_t lo0, lo1;
    uint32_t hi0 = split_hi(a0.x, a0.y, lo0);
    uint32_t hi1 = split_hi(a0.z, a0.w, lo1);
    *reinterpret_cast<uint2*>(outH + (size_t)node * HH + lane * 4) = make_uint2(hi0, hi1);
    *reinterpret_cast<uint2*>(outL + (size_t)node * HH + lane * 4) = make_uint2(lo0, lo1);
}

// ---------------------------------------------------------------------------
// Weights: transpose + split. out[m][n][k] = W_m[k][n]
// ---------------------------------------------------------------------------
__global__ void wconv_kernel(const float* __restrict__ W0, const float* __restrict__ W1,
                             const float* __restrict__ W2, const float* __restrict__ W3,
                             const float* __restrict__ W4, const float* __restrict__ W5,
                             __nv_bfloat16* __restrict__ wh, __nv_bfloat16* __restrict__ wl) {
    int i = blockIdx.x * blockDim.x + threadIdx.x;
    if (i >= 6 * HH * HH) return;
    int m = i / (HH * HH);
    int r = i % (HH * HH);
    int n = r / HH;
    int k = r % HH;
    const float* W = (m == 0) ? W0 : (m == 1) ? W1 : (m == 2) ? W2
                   : (m == 3) ? W3 : (m == 4) ? W4 : W5;
    float v = W[k * HH + n];
    __nv_bfloat16 h = __float2bfloat16(v);
    wh[i] = h;
    wl[i] = __float2bfloat16(v - __bfloat162float(h));
}

// ---------------------------------------------------------------------------
// Persistent fused MLP (R8 config, byte-exact): out = relu(A@W1+b1)@W2+b2
// 512 threads, 16 warps (4 rowgrp x 4 colgrp of 16x32), MTILE=64.
// A buffer + dedicated MID buffer (2 syncs/tile); A(t+1) prefetched under
// GEMM2. Biases via __ldg in epilogues (NOT hoisted — register pressure).
// Smem: A 34816 + MID 34816 + W1 69632 + W2 69632 = 208896 B.
// ---------------------------------------------------------------------------
#define PITCH 272
#define S_A   0
#define S_MID 34816
#define S_W1H 69632
#define S_W1L 104448
#define S_W2H 139264
#define S_W2L 174080
#define FUSED_SMEM 208896
#define MTILE 64
#define NTILES ((NN + MTILE - 1) / MTILE)   // 1563

__device__ __forceinline__ void run_gemm(uint32_t aHb, uint32_t aLb,
                                         uint32_t bHb, uint32_t bLb,
                                         float (&accH)[4][4], float (&accL)[4][4]) {
    #pragma unroll
    for (int i = 0; i < 4; i++)
        #pragma unroll
        for (int j = 0; j < 4; j++) { accH[i][j] = 0.f; accL[i][j] = 0.f; }
    #pragma unroll
    for (int ks = 0; ks < 8; ks++) {
        uint32_t aH[4], aL[4];
        ldsm4(aH, aHb + ks * 32);
        ldsm4(aL, aLb + ks * 32);
        #pragma unroll
        for (int np = 0; np < 2; np++) {
            uint32_t bh[4], bl[4];
            ldsm4(bh, bHb + np * (16 * PITCH) + ks * 32);
            ldsm4(bl, bLb + np * (16 * PITCH) + ks * 32);
            mma16816(accH[2 * np],     aH, bh[0], bh[2]);
            mma16816(accL[2 * np],     aL, bh[0], bh[2]);
            mma16816(accL[2 * np],     aH, bl[0], bl[2]);
            mma16816(accH[2 * np + 1], aH, bh[1], bh[3]);
            mma16816(accL[2 * np + 1], aL, bh[1], bh[3]);
            mma16816(accL[2 * np + 1], aH, bl[1], bl[3]);
        }
    }
}

__device__ __forceinline__ void prefetch_A(uint32_t sb, int tile,
                                           const __nv_bfloat16* __restrict__ AH,
                                           const __nv_bfloat16* __restrict__ AL,
                                           int M, int tid) {
    #pragma unroll
    for (int it = 0; it < 2; it++) {
        int idx = it * 512 + tid;       // 0..1023
        int row = idx >> 4, c = idx & 15;
        int gm = tile * MTILE + row;
        int ok = (gm < M) ? 16 : 0;
        int gs = min(gm, M - 1);
        uint32_t d = sb + S_A + row * PITCH + c * 16;
        cp16(d,         AH + (size_t)gs * HH + c * 8, ok);
        cp16(d + 17408, AL + (size_t)gs * HH + c * 8, ok);
    }
}

__global__ __launch_bounds__(512, 1)
void fused_mlp_persist(const __nv_bfloat16* __restrict__ AH,
                       const __nv_bfloat16* __restrict__ AL,
                       const __nv_bfloat16* __restrict__ W1h, const __nv_bfloat16* __restrict__ W1l,
                       const __nv_bfloat16* __restrict__ W2h, const __nv_bfloat16* __restrict__ W2l,
                       const float* __restrict__ bias1, const float* __restrict__ bias2,
                       float* __restrict__ Out, int M) {
    extern __shared__ __align__(16) char smem[];
    const uint32_t sb = smem_u32(smem);
    const int tid = threadIdx.x;
    const int wid = tid >> 5, lane = tid & 31;

    // ---- stage all weights once ----
    #pragma unroll
    for (int it = 0; it < 4; it++) {
        int idx = it * 512 + tid;       // 0..2047
        int row = idx >> 4, c = idx & 15;
        size_t go = (size_t)row * HH + c * 8;
        *reinterpret_cast<uint4*>(smem + S_W1H + row * PITCH + c * 16) =
            *reinterpret_cast<const uint4*>(W1h + go);
        *reinterpret_cast<uint4*>(smem + S_W1L + row * PITCH + c * 16) =
            *reinterpret_cast<const uint4*>(W1l + go);
        *reinterpret_cast<uint4*>(smem + S_W2H + row * PITCH + c * 16) =
            *reinterpret_cast<const uint4*>(W2h + go);
        *reinterpret_cast<uint4*>(smem + S_W2L + row * PITCH + c * 16) =
            *reinterpret_cast<const uint4*>(W2l + go);
    }

    int t = blockIdx.x;
    if (t < NTILES) prefetch_A(sb, t, AH, AL, M, tid);
    CP_COMMIT();

    const int wr = wid >> 2;            // 0..3 (16 rows each)
    const int wc = wid & 3;             // 0..3 (32 cols each)
    const int arow = lane & 15;
    const int akc  = (lane & 16) >> 1;  // 0 or 8
    const int quad = lane >> 2;
    const int qc   = (lane & 3) * 2;

    const uint32_t aHb = sb + S_A   + (wr * 16 + arow) * PITCH + akc * 2;
    const uint32_t aLb = aHb + 17408;
    const uint32_t mHb = sb + S_MID + (wr * 16 + arow) * PITCH + akc * 2;
    const uint32_t mLb = mHb + 17408;
    const uint32_t w1Hb = sb + S_W1H + (wc * 32 + arow) * PITCH + akc * 2;
    const uint32_t w1Lb = sb + S_W1L + (wc * 32 + arow) * PITCH + akc * 2;
    const uint32_t w2Hb = sb + S_W2H + (wc * 32 + arow) * PITCH + akc * 2;
    const uint32_t w2Lb = sb + S_W2L + (wc * 32 + arow) * PITCH + akc * 2;

    while (t < NTILES) {
        int tn = t + gridDim.x;
        CP_WAIT0();
        __syncthreads();                                  // B1: A(t) ready

        float accH[4][4], accL[4][4];

        // ---- GEMM1: A x W1 ----
        run_gemm(aHb, aLb, w1Hb, w1Lb, accH, accL);

        // ---- epilogue 1: relu(acc+b1) -> hi/lo -> MID buffer ----
        {
            const int lr0 = wr * 16 + quad;
            #pragma unroll
            for (int np = 0; np < 2; np++) {
                #pragma unroll
                for (int s = 0; s < 2; s++) {
                    int nt = 2 * np + s;
                    int col = wc * 32 + np * 16 + s * 8 + qc;
                    float b0 = __ldg(bias1 + col), b1v = __ldg(bias1 + col + 1);
                    float v00 = fmaxf(accH[nt][0] + accL[nt][0] + b0, 0.f);
                    float v01 = fmaxf(accH[nt][1] + accL[nt][1] + b1v, 0.f);
                    float v10 = fmaxf(accH[nt][2] + accL[nt][2] + b0, 0.f);
                    float v11 = fmaxf(accH[nt][3] + accL[nt][3] + b1v, 0.f);
                    uint32_t lo0, lo1;
                    uint32_t hi0 = split_hi(v00, v01, lo0);
                    uint32_t hi1 = split_hi(v10, v11, lo1);
                    char* mb = smem + S_MID;
                    *reinterpret_cast<uint32_t*>(mb + lr0 * PITCH + col * 2) = hi0;
                    *reinterpret_cast<uint32_t*>(mb + 17408 + lr0 * PITCH + col * 2) = lo0;
                    *reinterpret_cast<uint32_t*>(mb + (lr0 + 8) * PITCH + col * 2) = hi1;
                    *reinterpret_cast<uint32_t*>(mb + 17408 + (lr0 + 8) * PITCH + col * 2) = lo1;
                }
            }
        }
        __syncthreads();                                  // B2: mid visible, A reads done

        // prefetch next tile's A (hidden under GEMM2 + epilogue 2)
        if (tn < NTILES) prefetch_A(sb, tn, AH, AL, M, tid);
        CP_COMMIT();

        // ---- GEMM2: mid x W2 ----
        run_gemm(mHb, mLb, w2Hb, w2Lb, accH, accL);

        // ---- epilogue 2: + b2 -> fp32 gmem ----
        {
            const int r0 = t * MTILE + wr * 16 + quad;
            const int r1 = r0 + 8;
            #pragma unroll
            for (int np = 0; np < 2; np++) {
                #pragma unroll
                for (int s = 0; s < 2; s++) {
                    int nt = 2 * np + s;
                    int col = wc * 32 + np * 16 + s * 8 + qc;
                    float b0 = __ldg(bias2 + col), b1v = __ldg(bias2 + col + 1);
                    if (r0 < M)
                        *reinterpret_cast<float2*>(Out + (size_t)r0 * HH + col) =
                            make_float2(accH[nt][0] + accL[nt][0] + b0,
                                        accH[nt][1] + accL[nt][1] + b1v);
                    if (r1 < M)
                        *reinterpret_cast<float2*>(Out + (size_t)r1 * HH + col) =
                            make_float2(accH[nt][2] + accL[nt][2] + b0,
                                        accH[nt][3] + accL[nt][3] + b1v);
                }
            }
        }
        t = tn;
    }
}

// ---------------------------------------------------------------------------
// Pooling (batch sorted)
// ---------------------------------------------------------------------------
__global__ void pool_kernel(const float* __restrict__ h, const int* __restrict__ batch,
                            float* __restrict__ out, float* __restrict__ cnt) {
    __shared__ int sbv[128];
    const int b0 = blockIdx.x * 128;
    const int c = threadIdx.x;
    const int nrows = min(128, NN - b0);
    if (c < nrows) sbv[c] = batch[b0 + c];
    __syncthreads();

    int cur = sbv[0];
    float acc = 0.f, cn = 0.f;
    for (int i = 0; i < nrows; i++) {
        int g = sbv[i];
        if (g != cur) {
            atomicAdd(&out[cur * 128 + c], acc);
            if (c == 0) atomicAdd(&cnt[cur], cn);
            acc = 0.f; cn = 0.f; cur = g;
        }
        acc += h[(size_t)(b0 + i) * 128 + c];
        cn += 1.f;
    }
    atomicAdd(&out[cur * 128 + c], acc);
    if (c == 0) atomicAdd(&cnt[cur], cn);
}

__global__ void zero_out_kernel(float* __restrict__ out, float* __restrict__ cnt) {
    int i = blockIdx.x * blockDim.x + threadIdx.x;
    if (i < GG * HH) out[i] = 0.f;
    if (i < GG) cnt[i] = 0.f;
}

__global__ void div_kernel(float* __restrict__ out, const float* __restrict__ cnt) {
    int i = blockIdx.x * blockDim.x + threadIdx.x;
    if (i < GG * HH) out[i] /= fmaxf(cnt[i >> 7], 1.f);
}

// ---------------------------------------------------------------------------
// Launch
// ---------------------------------------------------------------------------
extern "C" void kernel_launch(void* const* d_in, const int* in_sizes, int n_in,
                              void* d_out, int out_size) {
    (void)in_sizes; (void)n_in; (void)out_size;

    const float* x          = (const float*)d_in[0];
    const int*   edge_index = (const int*)d_in[1];
    const int*   batch      = (const int*)d_in[2];
    const int*   e_src = edge_index;
    const int*   e_dst = edge_index + EE;
    float* out = (float*)d_out;

    void *ph, *paH, *paL, *pwH, *pwL, *pcnt, *pdeg, *prp, *phd, *pcs, *pbs;
    cudaGetSymbolAddress(&ph,  g_h);
    cudaGetSymbolAddress(&paH, g_aH);
    cudaGetSymbolAddress(&paL, g_aL);
    cudaGetSymbolAddress(&pwH, g_wH);
    cudaGetSymbolAddress(&pwL, g_wL);
    cudaGetSymbolAddress(&pcnt, g_cnt);
    cudaGetSymbolAddress(&pdeg, g_deg);
    cudaGetSymbolAddress(&prp,  g_rowptr);
    cudaGetSymbolAddress(&phd,  g_head);
    cudaGetSymbolAddress(&pcs,  g_csrc);
    cudaGetSymbolAddress(&pbs,  g_bsum);
    float* h  = (float*)ph;
    __nv_bfloat16* aH = (__nv_bfloat16*)paH;
    __nv_bfloat16* aL = (__nv_bfloat16*)paL;
    __nv_bfloat16* wH = (__nv_bfloat16*)pwH;
    __nv_bfloat16* wL = (__nv_bfloat16*)pwL;
    float* cnt = (float*)pcnt;
    int* deg    = (int*)pdeg;
    int* rowptr = (int*)prp;
    int* head   = (int*)phd;
    int* csrc   = (int*)pcs;
    int* bsum   = (int*)pbs;

    cudaFuncSetAttribute(fused_mlp_persist,
                         cudaFuncAttributeMaxDynamicSharedMemorySize, FUSED_SMEM);

    const int nn_blocks     = (NN + 255) / 256;
    const int ee_blocks     = (EE + 255) / 256;
    const int gather_blocks = (NN * 32 + 255) / 256;  // warp per node
    const int wconv_blocks  = (6 * HH * HH + 255) / 256;

    // ---- CSR build (once) ----
    zero_deg_kernel<<<nn_blocks, 256>>>(deg);
    hist_kernel<<<ee_blocks, 256>>>(e_dst, deg);
    scan1_kernel<<<SCAN_NB, SCAN_BLK>>>(deg, rowptr, bsum);
    scan3_kernel<<<nn_blocks, 256>>>(rowptr, head, bsum);
    fill_kernel<<<ee_blocks, 256>>>(e_src, e_dst, head, csrc);

    wconv_kernel<<<wconv_blocks, 256>>>((const float*)d_in[3], (const float*)d_in[5],
                                        (const float*)d_in[7], (const float*)d_in[9],
                                        (const float*)d_in[11], (const float*)d_in[13],
                                        wH, wL);

    const float* in = x;
    for (int l = 0; l < 3; l++) {
        const float* b1 = (const float*)d_in[3 + 4 * l + 1];
        const float* b2 = (const float*)d_in[3 + 4 * l + 3];
        __nv_bfloat16* w1H = wH + (size_t)(2 * l) * HH * HH;
        __nv_bfloat16* w1L = wL + (size_t)(2 * l) * HH * HH;
        __nv_bfloat16* w2H = wH + (size_t)(2 * l + 1) * HH * HH;
        __nv_bfloat16* w2L = wL + (size_t)(2 * l + 1) * HH * HH;

        gather_kernel<<<gather_blocks, 256>>>(in, csrc, rowptr, deg, aH, aL);
        fused_mlp_persist<<<148, 512, FUSED_SMEM>>>(
            aH, aL, w1H, w1L, w2H, w2L, b1, b2, h, NN);
        in = h;
    }

    zero_out_kernel<<<(GG * HH + 255) / 256, 256>>>(out, cnt);
    pool_kernel<<<(NN + 127) / 128, 128>>>(h, batch, out, cnt);
    div_kernel<<<(GG * HH + 255) / 256, 256>>>(out, cnt);
}

// round 16
// speedup vs baseline: 1.3478x; 1.0001x over previous
#include <cuda_runtime.h>
#include <cuda_bf16.h>
#include <cstdint>
#include <cstddef>

#define NN 100000
#define EE 1600000
#define HH 128
#define GG 128
#define SCAN_BLK 1024
#define SCAN_NB ((NN + SCAN_BLK - 1) / SCAN_BLK)   // 98

// ---------------------------------------------------------------------------
// Scratch (__device__ globals; allocation-free rule)
// ---------------------------------------------------------------------------
__device__ float g_h[(size_t)NN * HH];              // layer output (fp32)
__device__ __nv_bfloat16 g_aH[(size_t)NN * HH];     // xagg hi split
__device__ __nv_bfloat16 g_aL[(size_t)NN * HH];     // xagg lo split
__device__ __nv_bfloat16 g_wH[6 * HH * HH];         // transposed weights hi ([n][k])
__device__ __nv_bfloat16 g_wL[6 * HH * HH];         // transposed weights lo
__device__ float g_cnt[GG];
__device__ int g_deg[NN];
__device__ int g_rowptr[NN];
__device__ int g_head[NN];
__device__ int g_csrc[EE];
__device__ int g_bsum[SCAN_NB];

// ---------------------------------------------------------------------------
// helpers
// ---------------------------------------------------------------------------
__device__ __forceinline__ uint32_t smem_u32(const void* p) {
    uint32_t a;
    asm("{ .reg .u64 t; cvta.to.shared.u64 t, %1; cvt.u32.u64 %0, t; }" : "=r"(a) : "l"(p));
    return a;
}

__device__ __forceinline__ void ldsm4(uint32_t* r, uint32_t addr) {
    asm volatile("ldmatrix.sync.aligned.m8n8.x4.shared.b16 {%0,%1,%2,%3}, [%4];"
                 : "=r"(r[0]), "=r"(r[1]), "=r"(r[2]), "=r"(r[3]) : "r"(addr));
}

__device__ __forceinline__ void mma16816(float* c, const uint32_t* a, uint32_t b0, uint32_t b1) {
    asm volatile("mma.sync.aligned.m16n8k16.row.col.f32.bf16.bf16.f32 "
                 "{%0,%1,%2,%3}, {%4,%5,%6,%7}, {%8,%9}, {%0,%1,%2,%3};"
                 : "+f"(c[0]), "+f"(c[1]), "+f"(c[2]), "+f"(c[3])
                 : "r"(a[0]), "r"(a[1]), "r"(a[2]), "r"(a[3]), "r"(b0), "r"(b1));
}

__device__ __forceinline__ uint32_t pk(__nv_bfloat16 a, __nv_bfloat16 b) {
    __nv_bfloat162 t(a, b);
    return *reinterpret_cast<uint32_t*>(&t);
}

__device__ __forceinline__ uint32_t split_hi(float v0, float v1, uint32_t& lo) {
    __nv_bfloat16 h0 = __float2bfloat16(v0), h1 = __float2bfloat16(v1);
    lo = pk(__float2bfloat16(v0 - __bfloat162float(h0)),
            __float2bfloat16(v1 - __bfloat162float(h1)));
    return pk(h0, h1);
}

__device__ __forceinline__ void cp16(uint32_t dst, const void* src, int sz) {
    asm volatile("cp.async.cg.shared.global [%0], [%1], 16, %2;"
                 :: "r"(dst), "l"(src), "r"(sz) : "memory");
}
#define CP_COMMIT() asm volatile("cp.async.commit_group;" ::: "memory")
#define CP_WAIT0()  asm volatile("cp.async.wait_group 0;" ::: "memory")

// ---------------------------------------------------------------------------
// CSR build (once per launch): edges grouped by destination
// ---------------------------------------------------------------------------
__global__ void zero_deg_kernel(int* __restrict__ deg) {
    int i = blockIdx.x * blockDim.x + threadIdx.x;
    if (i < NN) deg[i] = 0;
}

__global__ void hist_kernel(const int* __restrict__ dst, int* __restrict__ deg) {
    int i = blockIdx.x * blockDim.x + threadIdx.x;
    if (i < EE) atomicAdd(&deg[dst[i]], 1);
}

__global__ void scan1_kernel(const int* __restrict__ deg, int* __restrict__ rowptr,
                             int* __restrict__ bsum) {
    __shared__ int sh[SCAN_BLK];
    int i = blockIdx.x * SCAN_BLK + threadIdx.x;
    int v = (i < NN) ? deg[i] : 0;
    sh[threadIdx.x] = v;
    __syncthreads();
    #pragma unroll
    for (int off = 1; off < SCAN_BLK; off <<= 1) {
        int t = (threadIdx.x >= off) ? sh[threadIdx.x - off] : 0;
        __syncthreads();
        sh[threadIdx.x] += t;
        __syncthreads();
    }
    if (i < NN) rowptr[i] = sh[threadIdx.x] - v;       // exclusive
    if (threadIdx.x == SCAN_BLK - 1) bsum[blockIdx.x] = sh[SCAN_BLK - 1];
}

// scan3 with the 98-element block-sum prefix computed redundantly per block
// (no separate scan2 launch).
__global__ void scan3_kernel(int* __restrict__ rowptr, int* __restrict__ head,
                             const int* __restrict__ bsum) {
    __shared__ int sh[128], ex[128];
    int tid = threadIdx.x;
    if (tid < 128) {
        int vv = (tid < SCAN_NB) ? bsum[tid] : 0;
        sh[tid] = vv;
        ex[tid] = vv;
    }
    __syncthreads();
    #pragma unroll
    for (int off = 1; off < 128; off <<= 1) {
        int t = (tid >= off && tid < 128) ? sh[tid - off] : 0;
        __syncthreads();
        if (tid < 128) sh[tid] += t;
        __syncthreads();
    }
    if (tid < 128) ex[tid] = sh[tid] - ex[tid];        // exclusive
    __syncthreads();
    int i = blockIdx.x * blockDim.x + tid;
    if (i < NN) {
        int r = rowptr[i] + ex[i >> 10];
        rowptr[i] = r;
        head[i] = r;
    }
}

__global__ void fill_kernel(const int* __restrict__ src, const int* __restrict__ dst,
                            int* __restrict__ head, int* __restrict__ csrc) {
    int i = blockIdx.x * blockDim.x + threadIdx.x;
    if (i < EE) {
        int pos = atomicAdd(&head[dst[i]], 1);
        csrc[pos] = src[i];
    }
}

// ---------------------------------------------------------------------------
// gather: warp per node. xagg[i] = in[i] + sum_{j in csr(i)} in[j]
// Output written as bf16 hi/lo split (MLP A-operand ready).
// ---------------------------------------------------------------------------
__global__ __launch_bounds__(256)
void gather_kernel(const float* __restrict__ In, const int* __restrict__ csrc,
                   const int* __restrict__ rowptr, const int* __restrict__ deg,
                   __nv_bfloat16* __restrict__ outH, __nv_bfloat16* __restrict__ outL) {
    int node = (blockIdx.x * blockDim.x + threadIdx.x) >> 5;
    int lane = threadIdx.x & 31;
    if (node >= NN) return;
    const float4* base = reinterpret_cast<const float4*>(In);

    float4 a0 = base[(size_t)node * 32 + lane];    // self term
    float4 a1 = make_float4(0.f, 0.f, 0.f, 0.f);
    float4 a2 = a1, a3 = a1;

    int st = rowptr[node];
    int dg = deg[node];
    int j = 0;
    for (; j + 4 <= dg; j += 4) {
        int s0 = __ldg(csrc + st + j);
        int s1 = __ldg(csrc + st + j + 1);
        int s2 = __ldg(csrc + st + j + 2);
        int s3 = __ldg(csrc + st + j + 3);
        float4 v0 = base[(size_t)s0 * 32 + lane];
        float4 v1 = base[(size_t)s1 * 32 + lane];
        float4 v2 = base[(size_t)s2 * 32 + lane];
        float4 v3 = base[(size_t)s3 * 32 + lane];
        a0.x += v0.x; a0.y += v0.y; a0.z += v0.z; a0.w += v0.w;
        a1.x += v1.x; a1.y += v1.y; a1.z += v1.z; a1.w += v1.w;
        a2.x += v2.x; a2.y += v2.y; a2.z += v2.z; a2.w += v2.w;
        a3.x += v3.x; a3.y += v3.y; a3.z += v3.z; a3.w += v3.w;
    }
    for (; j < dg; j++) {
        int s = __ldg(csrc + st + j);
        float4 v = base[(size_t)s * 32 + lane];
        a0.x += v.x; a0.y += v.y; a0.z += v.z; a0.w += v.w;
    }
    a0.x += a1.x + a2.x + a3.x;
    a0.y += a1.y + a2.y + a3.y;
    a0.z += a1.z + a2.z + a3.z;
    a0.w += a1.w + a2.w + a3.w;

    uint32_t lo0, lo1;
    uint32_t hi0 = split_hi(a0.x, a0.y, lo0);
    uint32_t hi1 = split_hi(a0.z, a0.w, lo1);
    *reinterpret_cast<uint2*>(outH + (size_t)node * HH + lane * 4) = make_uint2(hi0, hi1);
    *reinterpret_cast<uint2*>(outL + (size_t)node * HH + lane * 4) = make_uint2(lo0, lo1);
}

// ---------------------------------------------------------------------------
// Weights: transpose + split. out[m][n][k] = W_m[k][n]
// ---------------------------------------------------------------------------
__global__ void wconv_kernel(const float* __restrict__ W0, const float* __restrict__ W1,
                             const float* __restrict__ W2, const float* __restrict__ W3,
                             const float* __restrict__ W4, const float* __restrict__ W5,
                             __nv_bfloat16* __restrict__ wh, __nv_bfloat16* __restrict__ wl) {
    int i = blockIdx.x * blockDim.x + threadIdx.x;
    if (i >= 6 * HH * HH) return;
    int m = i / (HH * HH);
    int r = i % (HH * HH);
    int n = r / HH;
    int k = r % HH;
    const float* W = (m == 0) ? W0 : (m == 1) ? W1 : (m == 2) ? W2
                   : (m == 3) ? W3 : (m == 4) ? W4 : W5;
    float v = W[k * HH + n];
    __nv_bfloat16 h = __float2bfloat16(v);
    wh[i] = h;
    wl[i] = __float2bfloat16(v - __bfloat162float(h));
}

// ---------------------------------------------------------------------------
// Persistent fused MLP (R8 loop, byte-exact): out = relu(A@W1+b1)@W2+b2
// 512 threads, 16 warps (4 rowgrp x 4 colgrp of 16x32), MTILE=64.
// A buffer + dedicated MID buffer (2 syncs/tile); A(t+1) prefetched under
// GEMM2. One-time weight staging via cp.async, overlapped with A(0) prefetch.
// Smem: A 34816 + MID 34816 + W1 69632 + W2 69632 = 208896 B.
// ---------------------------------------------------------------------------
#define PITCH 272
#define S_A   0
#define S_MID 34816
#define S_W1H 69632
#define S_W1L 104448
#define S_W2H 139264
#define S_W2L 174080
#define FUSED_SMEM 208896
#define MTILE 64
#define NTILES ((NN + MTILE - 1) / MTILE)   // 1563

__device__ __forceinline__ void run_gemm(uint32_t aHb, uint32_t aLb,
                                         uint32_t bHb, uint32_t bLb,
                                         float (&accH)[4][4], float (&accL)[4][4]) {
    #pragma unroll
    for (int i = 0; i < 4; i++)
        #pragma unroll
        for (int j = 0; j < 4; j++) { accH[i][j] = 0.f; accL[i][j] = 0.f; }
    #pragma unroll
    for (int ks = 0; ks < 8; ks++) {
        uint32_t aH[4], aL[4];
        ldsm4(aH, aHb + ks * 32);
        ldsm4(aL, aLb + ks * 32);
        #pragma unroll
        for (int np = 0; np < 2; np++) {
            uint32_t bh[4], bl[4];
            ldsm4(bh, bHb + np * (16 * PITCH) + ks * 32);
            ldsm4(bl, bLb + np * (16 * PITCH) + ks * 32);
            mma16816(accH[2 * np],     aH, bh[0], bh[2]);
            mma16816(accL[2 * np],     aL, bh[0], bh[2]);
            mma16816(accL[2 * np],     aH, bl[0], bl[2]);
            mma16816(accH[2 * np + 1], aH, bh[1], bh[3]);
            mma16816(accL[2 * np + 1], aL, bh[1], bh[3]);
            mma16816(accL[2 * np + 1], aH, bl[1], bl[3]);
        }
    }
}

__device__ __forceinline__ void prefetch_A(uint32_t sb, int tile,
                                           const __nv_bfloat16* __restrict__ AH,
                                           const __nv_bfloat16* __restrict__ AL,
                                           int M, int tid) {
    #pragma unroll
    for (int it = 0; it < 2; it++) {
        int idx = it * 512 + tid;       // 0..1023
        int row = idx >> 4, c = idx & 15;
        int gm = tile * MTILE + row;
        int ok = (gm < M) ? 16 : 0;
        int gs = min(gm, M - 1);
        uint32_t d = sb + S_A + row * PITCH + c * 16;
        cp16(d,         AH + (size_t)gs * HH + c * 8, ok);
        cp16(d + 17408, AL + (size_t)gs * HH + c * 8, ok);
    }
}

__global__ __launch_bounds__(512, 1)
void fused_mlp_persist(const __nv_bfloat16* __restrict__ AH,
                       const __nv_bfloat16* __restrict__ AL,
                       const __nv_bfloat16* __restrict__ W1h, const __nv_bfloat16* __restrict__ W1l,
                       const __nv_bfloat16* __restrict__ W2h, const __nv_bfloat16* __restrict__ W2l,
                       const float* __restrict__ bias1, const float* __restrict__ bias2,
                       float* __restrict__ Out, int M) {
    extern __shared__ __align__(16) char smem[];
    const uint32_t sb = smem_u32(smem);
    const int tid = threadIdx.x;
    const int wid = tid >> 5, lane = tid & 31;

    // ---- stage all weights once (cp.async; overlapped with A(0) prefetch) ----
    #pragma unroll
    for (int it = 0; it < 4; it++) {
        int idx = it * 512 + tid;       // 0..2047
        int row = idx >> 4, c = idx & 15;
        size_t go = (size_t)row * HH + c * 8;
        uint32_t so = (uint32_t)(row * PITCH + c * 16);
        cp16(sb + S_W1H + so, W1h + go, 16);
        cp16(sb + S_W1L + so, W1l + go, 16);
        cp16(sb + S_W2H + so, W2h + go, 16);
        cp16(sb + S_W2L + so, W2l + go, 16);
    }

    int t = blockIdx.x;
    if (t < NTILES) prefetch_A(sb, t, AH, AL, M, tid);
    CP_COMMIT();

    const int wr = wid >> 2;            // 0..3 (16 rows each)
    const int wc = wid & 3;             // 0..3 (32 cols each)
    const int arow = lane & 15;
    const int akc  = (lane & 16) >> 1;  // 0 or 8
    const int quad = lane >> 2;
    const int qc   = (lane & 3) * 2;

    const uint32_t aHb = sb + S_A   + (wr * 16 + arow) * PITCH + akc * 2;
    const uint32_t aLb = aHb + 17408;
    const uint32_t mHb = sb + S_MID + (wr * 16 + arow) * PITCH + akc * 2;
    const uint32_t mLb = mHb + 17408;
    const uint32_t w1Hb = sb + S_W1H + (wc * 32 + arow) * PITCH + akc * 2;
    const uint32_t w1Lb = sb + S_W1L + (wc * 32 + arow) * PITCH + akc * 2;
    const uint32_t w2Hb = sb + S_W2H + (wc * 32 + arow) * PITCH + akc * 2;
    const uint32_t w2Lb = sb + S_W2L + (wc * 32 + arow) * PITCH + akc * 2;

    while (t < NTILES) {
        int tn = t + gridDim.x;
        CP_WAIT0();
        __syncthreads();                                  // B1: A(t) (+weights on iter 0) ready

        float accH[4][4], accL[4][4];

        // ---- GEMM1: A x W1 ----
        run_gemm(aHb, aLb, w1Hb, w1Lb, accH, accL);

        // ---- epilogue 1: relu(acc+b1) -> hi/lo -> MID buffer ----
        {
            const int lr0 = wr * 16 + quad;
            #pragma unroll
            for (int np = 0; np < 2; np++) {
                #pragma unroll
                for (int s = 0; s < 2; s++) {
                    int nt = 2 * np + s;
                    int col = wc * 32 + np * 16 + s * 8 + qc;
                    float b0 = __ldg(bias1 + col), b1v = __ldg(bias1 + col + 1);
                    float v00 = fmaxf(accH[nt][0] + accL[nt][0] + b0, 0.f);
                    float v01 = fmaxf(accH[nt][1] + accL[nt][1] + b1v, 0.f);
                    float v10 = fmaxf(accH[nt][2] + accL[nt][2] + b0, 0.f);
                    float v11 = fmaxf(accH[nt][3] + accL[nt][3] + b1v, 0.f);
                    uint32_t lo0, lo1;
                    uint32_t hi0 = split_hi(v00, v01, lo0);
                    uint32_t hi1 = split_hi(v10, v11, lo1);
                    char* mb = smem + S_MID;
                    *reinterpret_cast<uint32_t*>(mb + lr0 * PITCH + col * 2) = hi0;
                    *reinterpret_cast<uint32_t*>(mb + 17408 + lr0 * PITCH + col * 2) = lo0;
                    *reinterpret_cast<uint32_t*>(mb + (lr0 + 8) * PITCH + col * 2) = hi1;
                    *reinterpret_cast<uint32_t*>(mb + 17408 + (lr0 + 8) * PITCH + col * 2) = lo1;
                }
            }
        }
        __syncthreads();                                  // B2: mid visible, A reads done

        // prefetch next tile's A (hidden under GEMM2 + epilogue 2)
        if (tn < NTILES) prefetch_A(sb, tn, AH, AL, M, tid);
        CP_COMMIT();

        // ---- GEMM2: mid x W2 ----
        run_gemm(mHb, mLb, w2Hb, w2Lb, accH, accL);

        // ---- epilogue 2: + b2 -> fp32 gmem ----
        {
            const int r0 = t * MTILE + wr * 16 + quad;
            const int r1 = r0 + 8;
            #pragma unroll
            for (int np = 0; np < 2; np++) {
                #pragma unroll
                for (int s = 0; s < 2; s++) {
                    int nt = 2 * np + s;
                    int col = wc * 32 + np * 16 + s * 8 + qc;
                    float b0 = __ldg(bias2 + col), b1v = __ldg(bias2 + col + 1);
                    if (r0 < M)
                        *reinterpret_cast<float2*>(Out + (size_t)r0 * HH + col) =
                            make_float2(accH[nt][0] + accL[nt][0] + b0,
                                        accH[nt][1] + accL[nt][1] + b1v);
                    if (r1 < M)
                        *reinterpret_cast<float2*>(Out + (size_t)r1 * HH + col) =
                            make_float2(accH[nt][2] + accL[nt][2] + b0,
                                        accH[nt][3] + accL[nt][3] + b1v);
                }
            }
        }
        t = tn;
    }
}

// ---------------------------------------------------------------------------
// Pooling (batch sorted)
// ---------------------------------------------------------------------------
__global__ void pool_kernel(const float* __restrict__ h, const int* __restrict__ batch,
                            float* __restrict__ out, float* __restrict__ cnt) {
    __shared__ int sbv[128];
    const int b0 = blockIdx.x * 128;
    const int c = threadIdx.x;
    const int nrows = min(128, NN - b0);
    if (c < nrows) sbv[c] = batch[b0 + c];
    __syncthreads();

    int cur = sbv[0];
    float acc = 0.f, cn = 0.f;
    for (int i = 0; i < nrows; i++) {
        int g = sbv[i];
        if (g != cur) {
            atomicAdd(&out[cur * 128 + c], acc);
            if (c == 0) atomicAdd(&cnt[cur], cn);
            acc = 0.f; cn = 0.f; cur = g;
        }
        acc += h[(size_t)(b0 + i) * 128 + c];
        cn += 1.f;
    }
    atomicAdd(&out[cur * 128 + c], acc);
    if (c == 0) atomicAdd(&cnt[cur], cn);
}

__global__ void zero_out_kernel(float* __restrict__ out, float* __restrict__ cnt) {
    int i = blockIdx.x * blockDim.x + threadIdx.x;
    if (i < GG * HH) out[i] = 0.f;
    if (i < GG) cnt[i] = 0.f;
}

__global__ void div_kernel(float* __restrict__ out, const float* __restrict__ cnt) {
    int i = blockIdx.x * blockDim.x + threadIdx.x;
    if (i < GG * HH) out[i] /= fmaxf(cnt[i >> 7], 1.f);
}

// ---------------------------------------------------------------------------
// Launch
// ---------------------------------------------------------------------------
extern "C" void kernel_launch(void* const* d_in, const int* in_sizes, int n_in,
                              void* d_out, int out_size) {
    (void)in_sizes; (void)n_in; (void)out_size;

    const float* x          = (const float*)d_in[0];
    const int*   edge_index = (const int*)d_in[1];
    const int*   batch      = (const int*)d_in[2];
    const int*   e_src = edge_index;
    const int*   e_dst = edge_index + EE;
    float* out = (float*)d_out;

    void *ph, *paH, *paL, *pwH, *pwL, *pcnt, *pdeg, *prp, *phd, *pcs, *pbs;
    cudaGetSymbolAddress(&ph,  g_h);
    cudaGetSymbolAddress(&paH, g_aH);
    cudaGetSymbolAddress(&paL, g_aL);
    cudaGetSymbolAddress(&pwH, g_wH);
    cudaGetSymbolAddress(&pwL, g_wL);
    cudaGetSymbolAddress(&pcnt, g_cnt);
    cudaGetSymbolAddress(&pdeg, g_deg);
    cudaGetSymbolAddress(&prp,  g_rowptr);
    cudaGetSymbolAddress(&phd,  g_head);
    cudaGetSymbolAddress(&pcs,  g_csrc);
    cudaGetSymbolAddress(&pbs,  g_bsum);
    float* h  = (float*)ph;
    __nv_bfloat16* aH = (__nv_bfloat16*)paH;
    __nv_bfloat16* aL = (__nv_bfloat16*)paL;
    __nv_bfloat16* wH = (__nv_bfloat16*)pwH;
    __nv_bfloat16* wL = (__nv_bfloat16*)pwL;
    float* cnt = (float*)pcnt;
    int* deg    = (int*)pdeg;
    int* rowptr = (int*)prp;
    int* head   = (int*)phd;
    int* csrc   = (int*)pcs;
    int* bsum   = (int*)pbs;

    cudaFuncSetAttribute(fused_mlp_persist,
                         cudaFuncAttributeMaxDynamicSharedMemorySize, FUSED_SMEM);

    const int nn_blocks     = (NN + 255) / 256;
    const int ee_blocks     = (EE + 255) / 256;
    const int gather_blocks = (NN * 32 + 255) / 256;  // warp per node
    const int wconv_blocks  = (6 * HH * HH + 255) / 256;

    // ---- CSR build (once) ----
    zero_deg_kernel<<<nn_blocks, 256>>>(deg);
    hist_kernel<<<ee_blocks, 256>>>(e_dst, deg);
    scan1_kernel<<<SCAN_NB, SCAN_BLK>>>(deg, rowptr, bsum);
    scan3_kernel<<<nn_blocks, 256>>>(rowptr, head, bsum);
    fill_kernel<<<ee_blocks, 256>>>(e_src, e_dst, head, csrc);

    wconv_kernel<<<wconv_blocks, 256>>>((const float*)d_in[3], (const float*)d_in[5],
                                        (const float*)d_in[7], (const float*)d_in[9],
                                        (const float*)d_in[11], (const float*)d_in[13],
                                        wH, wL);

    const float* in = x;
    for (int l = 0; l < 3; l++) {
        const float* b1 = (const float*)d_in[3 + 4 * l + 1];
        const float* b2 = (const float*)d_in[3 + 4 * l + 3];
        __nv_bfloat16* w1H = wH + (size_t)(2 * l) * HH * HH;
        __nv_bfloat16* w1L = wL + (size_t)(2 * l) * HH * HH;
        __nv_bfloat16* w2H = wH + (size_t)(2 * l + 1) * HH * HH;
        __nv_bfloat16* w2L = wL + (size_t)(2 * l + 1) * HH * HH;

        gather_kernel<<<gather_blocks, 256>>>(in, csrc, rowptr, deg, aH, aL);
        fused_mlp_persist<<<148, 512, FUSED_SMEM>>>(
            aH, aL, w1H, w1L, w2H, w2L, b1, b2, h, NN);
        in = h;
    }

    zero_out_kernel<<<(GG * HH + 255) / 256, 256>>>(out, cnt);
    pool_kernel<<<(NN + 127) / 128, 128>>>(h, batch, out, cnt);
    div_kernel<<<(GG * HH + 255) / 256, 256>>>(out, cnt);
}